// round 4
// baseline (speedup 1.0000x reference)
#include <cuda_runtime.h>
#include <math.h>

// Problem constants
constexpr int Bb = 64;          // batch
constexpr int Ss = 512;         // src_len
constexpr int Hh = 1024;        // HID
constexpr int Kd = 2048;        // 2*HID
constexpr int Mm = Bb * Ss;     // 32768 GEMM rows (m = s*64 + b, contiguous in enc)
#define NEGV -1e10f

// Scratch (no cudaMalloc allowed)
__device__ float g_Wh[Bb * Hh];                 // 256 KB
__device__ float g_partial[(size_t)Mm * 8];     // 1 MB: partial energies per N-block

// ---------------------------------------------------------------------------
// Kernel 1: Wh = hidden @ W_w^T + W_b    [64,1024]
// grid (64, 4), 256 threads: one h per thread
// ---------------------------------------------------------------------------
__global__ void wh_kernel(const float* __restrict__ hidden,
                          const float* __restrict__ W_w,
                          const float* __restrict__ W_b) {
    __shared__ float sh[Hh];
    int b = blockIdx.x;
    int h = blockIdx.y * 256 + threadIdx.x;
    for (int i = threadIdx.x; i < Hh; i += 256)
        sh[i] = hidden[b * Hh + i];
    __syncthreads();
    const float4* wr = reinterpret_cast<const float4*>(W_w + (size_t)h * Hh);
    float acc = W_b[h];
#pragma unroll 8
    for (int k4 = 0; k4 < Hh / 4; ++k4) {
        float4 w = wr[k4];
        acc += sh[4*k4+0]*w.x + sh[4*k4+1]*w.y + sh[4*k4+2]*w.z + sh[4*k4+3]*w.w;
    }
    g_Wh[b * Hh + h] = acc;
}

// ---------------------------------------------------------------------------
// Kernel 2: fused GEMM + tanh + dot-v epilogue.
//   C[m,h] = sum_e enc[m,e] * U_w[h,e]
//   partial[m, nb] = sum_{h in nb-block} v[h]*tanh(C[m,h] + Wh[b,h] + U_b[h])
// 128x128x8 tile, double-buffered smem, 8x8 microtile, 256 threads.
// grid (Mm/128 = 256, Hh/128 = 8)
// ---------------------------------------------------------------------------
__global__ void __launch_bounds__(256, 2)
gemm_energy_kernel(const float* __restrict__ enc,   // [Mm, Kd] row-major
                   const float* __restrict__ U_w,   // [Hh, Kd] row-major
                   const float* __restrict__ U_b,   // [Hh]
                   const float* __restrict__ v)     // [Hh]
{
    constexpr int BM = 128, BN = 128, BK = 8;
    __shared__ __align__(16) float As[2][BK][BM];
    __shared__ __align__(16) float Bs[2][BK][BN];
    __shared__ float sred[16][128];

    const int m0 = blockIdx.x * BM;
    const int n0 = blockIdx.y * BN;
    const int tid = threadIdx.x;
    const int tx = tid & 15;        // column group (N)
    const int ty = tid >> 4;        // row group (M)

    // global->smem load mapping: one float4 per thread per operand
    const int lrow = tid >> 1;          // 0..127
    const int lk   = (tid & 1) * 4;     // 0 or 4

    const float* Aptr = enc + (size_t)(m0 + lrow) * Kd + lk;
    const float* Bptr = U_w + (size_t)(n0 + lrow) * Kd + lk;

    float acc[8][8];
#pragma unroll
    for (int i = 0; i < 8; ++i)
#pragma unroll
        for (int j = 0; j < 8; ++j) acc[i][j] = 0.0f;

    // prologue: stage 0
    float4 ra = *reinterpret_cast<const float4*>(Aptr);
    float4 rb = *reinterpret_cast<const float4*>(Bptr);
    As[0][lk+0][lrow] = ra.x; As[0][lk+1][lrow] = ra.y;
    As[0][lk+2][lrow] = ra.z; As[0][lk+3][lrow] = ra.w;
    Bs[0][lk+0][lrow] = rb.x; Bs[0][lk+1][lrow] = rb.y;
    Bs[0][lk+2][lrow] = rb.z; Bs[0][lk+3][lrow] = rb.w;
    __syncthreads();

    const int NT = Kd / BK;   // 256 stages
    for (int t = 0; t < NT; ++t) {
        const int buf = t & 1;
        if (t + 1 < NT) {
            ra = *reinterpret_cast<const float4*>(Aptr + (t + 1) * BK);
            rb = *reinterpret_cast<const float4*>(Bptr + (t + 1) * BK);
        }
#pragma unroll
        for (int k = 0; k < BK; ++k) {
            const float4* pa = reinterpret_cast<const float4*>(&As[buf][k][ty * 8]);
            const float4* pb = reinterpret_cast<const float4*>(&Bs[buf][k][tx * 8]);
            float4 a0 = pa[0], a1 = pa[1];
            float4 b0 = pb[0], b1 = pb[1];
            float af[8] = {a0.x, a0.y, a0.z, a0.w, a1.x, a1.y, a1.z, a1.w};
            float bf[8] = {b0.x, b0.y, b0.z, b0.w, b1.x, b1.y, b1.z, b1.w};
#pragma unroll
            for (int i = 0; i < 8; ++i)
#pragma unroll
                for (int j = 0; j < 8; ++j)
                    acc[i][j] = fmaf(af[i], bf[j], acc[i][j]);
        }
        if (t + 1 < NT) {
            const int nbuf = buf ^ 1;
            As[nbuf][lk+0][lrow] = ra.x; As[nbuf][lk+1][lrow] = ra.y;
            As[nbuf][lk+2][lrow] = ra.z; As[nbuf][lk+3][lrow] = ra.w;
            Bs[nbuf][lk+0][lrow] = rb.x; Bs[nbuf][lk+1][lrow] = rb.y;
            Bs[nbuf][lk+2][lrow] = rb.z; Bs[nbuf][lk+3][lrow] = rb.w;
            __syncthreads();
        }
    }

    // epilogue: pe[i] = sum_j v[h]*tanh(acc + Wh[b,h] + U_b[h])
    float pe[8];
#pragma unroll
    for (int i = 0; i < 8; ++i) pe[i] = 0.0f;
#pragma unroll
    for (int j = 0; j < 8; ++j) {
        const int h = n0 + tx * 8 + j;
        const float vh = v[h];
        const float ub = U_b[h];
#pragma unroll
        for (int i = 0; i < 8; ++i) {
            const int r  = ty * 8 + i;            // m = m0 + r ; b = m & 63 (m0 mult of 128)
            const int bb = r & 63;
            float arg = acc[i][j] + g_Wh[bb * Hh + h] + ub;
            pe[i] += vh * tanhf(arg);
        }
    }

    // deterministic cross-tx reduction via smem
#pragma unroll
    for (int i = 0; i < 8; ++i) sred[tx][ty * 8 + i] = pe[i];
    __syncthreads();
    if (tid < 128) {
        float s = 0.0f;
#pragma unroll
        for (int t2 = 0; t2 < 16; ++t2) s += sred[t2][tid];
        g_partial[(size_t)(m0 + tid) * 8 + blockIdx.y] = s;
    }
}

// ---------------------------------------------------------------------------
// Kernel 3: masked softmax over S per batch. grid 64, block 512 (1 thread/s).
// Mask read as int32 (harness normalizes bool -> int32; nonzero test also
// covers a float32 0.0/1.0 encoding since 1.0f has a nonzero bit pattern).
// ---------------------------------------------------------------------------
__global__ void softmax_kernel(const int* __restrict__ mask,
                               float* __restrict__ out)
{
    const int b = blockIdx.x;
    const int s = threadIdx.x;       // 0..511
    const int m = s * Bb + b;
    float e = 0.0f;
#pragma unroll
    for (int nb = 0; nb < 8; ++nb) e += g_partial[(size_t)m * 8 + nb];
    if (mask[b * Ss + s] != 0) e = NEGV;  // mask==true -> excluded (matches jnp.where)

    __shared__ float red[512];
    red[s] = e;
    __syncthreads();
    for (int off = 256; off > 0; off >>= 1) {
        if (s < off) red[s] = fmaxf(red[s], red[s + off]);
        __syncthreads();
    }
    const float mx = red[0];
    __syncthreads();
    const float ex = __expf(e - mx);
    red[s] = ex;
    __syncthreads();
    for (int off = 256; off > 0; off >>= 1) {
        if (s < off) red[s] += red[s + off];
        __syncthreads();
    }
    out[b * Ss + s] = ex / red[0];
}

// ---------------------------------------------------------------------------
extern "C" void kernel_launch(void* const* d_in, const int* in_sizes, int n_in,
                              void* d_out, int out_size) {
    const float* hidden = (const float*)d_in[0];
    const float* enc    = (const float*)d_in[1];  // [S,B,2H] == [Mm,Kd]
    const int*   mask   = (const int*)d_in[2];
    const float* W_w    = (const float*)d_in[3];
    const float* W_b    = (const float*)d_in[4];
    const float* U_w    = (const float*)d_in[5];
    const float* U_b    = (const float*)d_in[6];
    const float* v_w    = (const float*)d_in[7];
    float* out = (float*)d_out;

    wh_kernel<<<dim3(Bb, 4), 256>>>(hidden, W_w, W_b);
    gemm_energy_kernel<<<dim3(Mm / 128, Hh / 128), 256>>>(enc, U_w, U_b, v_w);
    softmax_kernel<<<Bb, 512>>>(mask, out);
}

// round 6
// speedup vs baseline: 4.2210x; 4.2210x over previous
#include <cuda_runtime.h>
#include <cstdint>
#include <math.h>

// Problem constants
constexpr int Bb = 64, Ss = 512, Hh = 1024, Kd = 2048, Mm = Bb * Ss;
#define NEGV -1e10f

// Scratch (no cudaMalloc allowed)
__device__ float g_WhT[Hh * Bb];      // WhT[h*64+b] = hidden@W^T + W_b + U_b (folded)
__device__ float g_partial[Mm * 4];   // per-(m, n-block) energy partials

// ---------------- GEMM tiling ----------------
constexpr int BM = 128, BN = 256, BK = 32;
constexpr int NSTG = Kd / BK;                 // 64 K-stages
constexpr int A_BYTES = BM * BK * 4;          // 16 KB
constexpr int B_BYTES = BN * BK * 4;          // 32 KB
constexpr int STG_BYTES = A_BYTES + B_BYTES;  // 48 KB
constexpr int GEMM_SMEM = 3 * STG_BYTES;      // 144 KB (3-stage pipeline)

// ---------------- helpers ----------------
__device__ __forceinline__ uint32_t smem_u32(const void* p) {
    uint32_t a;
    asm("{ .reg .u64 t; cvta.to.shared.u64 t, %1; cvt.u32.u64 %0, t; }" : "=r"(a) : "l"(p));
    return a;
}
__device__ __forceinline__ void cp16(uint32_t dst, const void* src) {
    asm volatile("cp.async.cg.shared.global [%0], [%1], 16;" :: "r"(dst), "l"(src));
}
__device__ __forceinline__ void cp_commit() {
    asm volatile("cp.async.commit_group;" ::: "memory");
}
template <int N> __device__ __forceinline__ void cp_wait() {
    asm volatile("cp.async.wait_group %0;" :: "n"(N) : "memory");
}
__device__ __forceinline__ uint32_t f2tf(float x) {
    uint32_t r;
    asm("cvt.rna.tf32.f32 %0, %1;" : "=r"(r) : "f"(x));
    return r;
}
__device__ __forceinline__ void mma_tf32(float c[4], uint32_t a0, uint32_t a1,
                                         uint32_t a2, uint32_t a3,
                                         uint32_t b0, uint32_t b1) {
    asm volatile("mma.sync.aligned.m16n8k8.row.col.f32.tf32.tf32.f32 "
                 "{%0,%1,%2,%3}, {%4,%5,%6,%7}, {%8,%9}, {%0,%1,%2,%3};"
                 : "+f"(c[0]), "+f"(c[1]), "+f"(c[2]), "+f"(c[3])
                 : "r"(a0), "r"(a1), "r"(a2), "r"(a3), "r"(b0), "r"(b1));
}
// swizzled 16B-chunk offset within a tile: row-major rows of 8 chunks, chunk
// column XOR'd with (row&7) -> fragment LDS and cp.async STS both conflict-free
__device__ __forceinline__ uint32_t tile_off(int row, int kc) {
    return (uint32_t)((row * 8 + (kc ^ (row & 7))) * 16);
}

// ---------------------------------------------------------------------------
// Kernel 1: g_WhT[h*64+b] = hidden[b,:]·W_w[h,:] + W_b[h] + U_b[h]
// grid (128, 8): block = 8 h x 8 b; warp w -> h = h0+w over 8 b's.
// ---------------------------------------------------------------------------
__global__ void __launch_bounds__(256, 4)
wh_kernel2(const float* __restrict__ hidden, const float* __restrict__ W_w,
           const float* __restrict__ W_b, const float* __restrict__ U_b) {
    __shared__ float4 sh[8][256];
    const int h0 = blockIdx.x * 8, b0 = blockIdx.y * 8;
    const int tid = threadIdx.x;
    for (int i = tid; i < 8 * 256; i += 256) {
        int bl = i >> 8, k4 = i & 255;
        sh[bl][k4] = reinterpret_cast<const float4*>(hidden)[(size_t)(b0 + bl) * 256 + k4];
    }
    __syncthreads();
    const int w = tid >> 5, lane = tid & 31;
    const int h = h0 + w;
    const float4* wrow = reinterpret_cast<const float4*>(W_w) + (size_t)h * 256;
    float acc[8] = {0.f, 0.f, 0.f, 0.f, 0.f, 0.f, 0.f, 0.f};
    for (int k4 = lane; k4 < 256; k4 += 32) {
        float4 wv = wrow[k4];
#pragma unroll
        for (int b = 0; b < 8; ++b) {
            float4 hv = sh[b][k4];
            acc[b] += wv.x * hv.x + wv.y * hv.y + wv.z * hv.z + wv.w * hv.w;
        }
    }
#pragma unroll
    for (int off = 16; off > 0; off >>= 1)
#pragma unroll
        for (int b = 0; b < 8; ++b) acc[b] += __shfl_xor_sync(0xffffffffu, acc[b], off);
    if (lane < 8)
        g_WhT[(size_t)h * 64 + b0 + lane] = acc[lane] + W_b[h] + U_b[h];
}

// ---------------------------------------------------------------------------
// Kernel 2: tf32 mma.sync GEMM (BM=128, BN=256, K=2048) + fused v·tanh epilogue.
// 256 threads = 8 warps (2m x 4n), warp tile 64x64, m16n8k8.
// grid (Mm/128 = 256, Hh/256 = 4).
// ---------------------------------------------------------------------------
__global__ void __launch_bounds__(256, 1)
gemm_energy_mma(const float* __restrict__ enc, const float* __restrict__ U_w,
                const float* __restrict__ v) {
    extern __shared__ char smem[];
    const uint32_t sbase = smem_u32(smem);

    const int tid = threadIdx.x;
    const int m0 = blockIdx.x * BM;
    const int n0 = blockIdx.y * BN;

    // ---- cp.async geometry: chunk idx = tid + i*256; row = idx>>3, kc = idx&7.
    // i-increment: row += 32 -> src += 32*Kd floats, dst += 32*8*16 bytes (row&7 fixed).
    const int crow = tid >> 3, ckc = tid & 7;
    const char* srcA0 = (const char*)(enc + (size_t)(m0 + crow) * Kd + ckc * 4);
    const char* srcB0 = (const char*)(U_w + (size_t)(n0 + crow) * Kd + ckc * 4);
    const uint32_t dstA0 = tile_off(crow, ckc);
    const uint32_t dstB0 = (uint32_t)A_BYTES + tile_off(crow, ckc);
    constexpr size_t SRC_STEP = (size_t)32 * Kd * 4;   // bytes per i
    constexpr uint32_t DST_STEP = 32 * 8 * 16;         // 4096 bytes per i

    auto load_stage = [&](int t) {
        const uint32_t base = sbase + (uint32_t)(t % 3) * STG_BYTES;
        const size_t ko = (size_t)t * (BK * 4);
#pragma unroll
        for (int i = 0; i < 4; ++i)
            cp16(base + dstA0 + i * DST_STEP, srcA0 + ko + i * SRC_STEP);
#pragma unroll
        for (int i = 0; i < 8; ++i)
            cp16(base + dstB0 + i * DST_STEP, srcB0 + ko + i * SRC_STEP);
        cp_commit();
    };

    load_stage(0);
    load_stage(1);

    const int wid = tid >> 5, lane = tid & 31;
    const int wm = wid >> 2, wn = wid & 3;     // warp grid 2(m) x 4(n)
    const int gid = lane >> 2, tig = lane & 3;

    float c[4][8][4];
#pragma unroll
    for (int mt = 0; mt < 4; ++mt)
#pragma unroll
        for (int nt = 0; nt < 8; ++nt)
#pragma unroll
            for (int k = 0; k < 4; ++k) c[mt][nt][k] = 0.f;

    for (int t = 0; t < NSTG; ++t) {
        if (t + 2 < NSTG) { load_stage(t + 2); cp_wait<2>(); }
        else if (t + 1 < NSTG) cp_wait<1>();
        else cp_wait<0>();
        __syncthreads();

        const char* As = smem + (t % 3) * STG_BYTES;
        const char* Bs = As + A_BYTES;

#pragma unroll
        for (int ks = 0; ks < 4; ++ks) {
            const int kc0 = ks * 2, kc1 = ks * 2 + 1;
            uint32_t a[4][4];
#pragma unroll
            for (int mt = 0; mt < 4; ++mt) {
                const int r0 = wm * 64 + mt * 16 + gid;
                a[mt][0] = f2tf(*(const float*)(As + tile_off(r0,     kc0) + tig * 4));
                a[mt][1] = f2tf(*(const float*)(As + tile_off(r0 + 8, kc0) + tig * 4));
                a[mt][2] = f2tf(*(const float*)(As + tile_off(r0,     kc1) + tig * 4));
                a[mt][3] = f2tf(*(const float*)(As + tile_off(r0 + 8, kc1) + tig * 4));
            }
            uint32_t b[8][2];
#pragma unroll
            for (int nt = 0; nt < 8; ++nt) {
                const int nr = wn * 64 + nt * 8 + gid;
                b[nt][0] = f2tf(*(const float*)(Bs + tile_off(nr, kc0) + tig * 4));
                b[nt][1] = f2tf(*(const float*)(Bs + tile_off(nr, kc1) + tig * 4));
            }
#pragma unroll
            for (int mt = 0; mt < 4; ++mt)
#pragma unroll
                for (int nt = 0; nt < 8; ++nt)
                    mma_tf32(c[mt][nt], a[mt][0], a[mt][1], a[mt][2], a[mt][3],
                             b[nt][0], b[nt][1]);
        }
        __syncthreads();
    }

    // ---- fused epilogue: pe = sum over held cols of v[h]*tanh(C + WhT[h][b])
    // C layout: c0,c1 -> row gid, cols 2tig,2tig+1 ; c2,c3 -> row gid+8.
    float pe[4][2];
#pragma unroll
    for (int mt = 0; mt < 4; ++mt) { pe[mt][0] = 0.f; pe[mt][1] = 0.f; }

#pragma unroll
    for (int nt = 0; nt < 8; ++nt) {
        const int h0 = n0 + wn * 64 + nt * 8 + 2 * tig;
        const float vh0 = __ldg(&v[h0]);
        const float vh1 = __ldg(&v[h0 + 1]);
#pragma unroll
        for (int mt = 0; mt < 4; ++mt) {
#pragma unroll
            for (int half = 0; half < 2; ++half) {
                const int b = mt * 16 + half * 8 + gid;       // (m0+row)&63, wm drops out
                const float w0 = __ldg(&g_WhT[(size_t)h0 * 64 + b]);
                const float w1 = __ldg(&g_WhT[(size_t)(h0 + 1) * 64 + b]);
                pe[mt][half] += vh0 * tanhf(c[mt][nt][half * 2 + 0] + w0)
                              + vh1 * tanhf(c[mt][nt][half * 2 + 1] + w1);
            }
        }
    }

    float* sred = (float*)smem;   // reuse tile smem (mainloop finished, post-sync)
#pragma unroll
    for (int mt = 0; mt < 4; ++mt)
#pragma unroll
        for (int half = 0; half < 2; ++half) {
            float s = pe[mt][half];
            s += __shfl_xor_sync(0xffffffffu, s, 1);
            s += __shfl_xor_sync(0xffffffffu, s, 2);
            if (tig == 0)
                sred[wn * 128 + wm * 64 + mt * 16 + half * 8 + gid] = s;
        }
    __syncthreads();
    if (tid < 128) {
        float s = sred[tid] + sred[128 + tid] + sred[256 + tid] + sred[384 + tid];
        g_partial[(size_t)(m0 + tid) * 4 + blockIdx.y] = s;
    }
}

// ---------------------------------------------------------------------------
// Kernel 3: masked softmax over S per batch. grid 64, block 512.
// ---------------------------------------------------------------------------
__global__ void softmax_kernel(const int* __restrict__ mask, float* __restrict__ out) {
    const int b = blockIdx.x;
    const int s = threadIdx.x;
    const int m = s * Bb + b;
    float e = g_partial[(size_t)m * 4 + 0] + g_partial[(size_t)m * 4 + 1]
            + g_partial[(size_t)m * 4 + 2] + g_partial[(size_t)m * 4 + 3];
    if (mask[b * Ss + s] != 0) e = NEGV;

    __shared__ float red[512];
    red[s] = e;
    __syncthreads();
    for (int off = 256; off > 0; off >>= 1) {
        if (s < off) red[s] = fmaxf(red[s], red[s + off]);
        __syncthreads();
    }
    const float mx = red[0];
    __syncthreads();
    const float ex = __expf(e - mx);
    red[s] = ex;
    __syncthreads();
    for (int off = 256; off > 0; off >>= 1) {
        if (s < off) red[s] += red[s + off];
        __syncthreads();
    }
    out[b * Ss + s] = ex / red[0];
}

// ---------------------------------------------------------------------------
extern "C" void kernel_launch(void* const* d_in, const int* in_sizes, int n_in,
                              void* d_out, int out_size) {
    const float* hidden = (const float*)d_in[0];
    const float* enc    = (const float*)d_in[1];   // [S,B,2H] == [Mm,Kd]
    const int*   mask   = (const int*)d_in[2];
    const float* W_w    = (const float*)d_in[3];
    const float* W_b    = (const float*)d_in[4];
    const float* U_w    = (const float*)d_in[5];
    const float* U_b    = (const float*)d_in[6];
    const float* v_w    = (const float*)d_in[7];
    float* out = (float*)d_out;

    cudaFuncSetAttribute(gemm_energy_mma, cudaFuncAttributeMaxDynamicSharedMemorySize,
                         GEMM_SMEM);

    wh_kernel2<<<dim3(Hh / 8, Bb / 8), 256>>>(hidden, W_w, W_b, U_b);
    gemm_energy_mma<<<dim3(Mm / BM, Hh / BN), 256, GEMM_SMEM>>>(enc, U_w, v_w);
    softmax_kernel<<<Bb, 512>>>(mask, out);
}

// round 7
// speedup vs baseline: 4.3547x; 1.0317x over previous
#include <cuda_runtime.h>
#include <cstdint>
#include <math.h>

// Problem constants
constexpr int Bb = 64, Ss = 512, Hh = 1024, Kd = 2048, Mm = Bb * Ss;
#define NEGV -1e10f

// Scratch (no cudaMalloc allowed)
__device__ float g_WhT[Hh * Bb];      // WhT[h*64+b] = hidden@W^T + W_b + U_b (folded)
__device__ float g_partial[Mm * 4];   // per-(m, n-block) energy partials

// ---------------- GEMM tiling ----------------
constexpr int BM = 128, BN = 256, BK = 32;
constexpr int NSTG = Kd / BK;                 // 64 K-stages
constexpr int A_BYTES = BM * BK * 4;          // 16 KB
constexpr int B_BYTES = BN * BK * 4;          // 32 KB
constexpr int STG_BYTES = A_BYTES + B_BYTES;  // 48 KB
constexpr int GEMM_SMEM = 3 * STG_BYTES;      // 144 KB (3-stage pipeline)

// ---------------- helpers ----------------
__device__ __forceinline__ uint32_t smem_u32(const void* p) {
    uint32_t a;
    asm("{ .reg .u64 t; cvta.to.shared.u64 t, %1; cvt.u32.u64 %0, t; }" : "=r"(a) : "l"(p));
    return a;
}
__device__ __forceinline__ void cp16(uint32_t dst, const void* src) {
    asm volatile("cp.async.cg.shared.global [%0], [%1], 16;" :: "r"(dst), "l"(src));
}
__device__ __forceinline__ void cp_commit() {
    asm volatile("cp.async.commit_group;" ::: "memory");
}
template <int N> __device__ __forceinline__ void cp_wait() {
    asm volatile("cp.async.wait_group %0;" :: "n"(N) : "memory");
}
__device__ __forceinline__ void ldm4(uint32_t& d0, uint32_t& d1, uint32_t& d2,
                                     uint32_t& d3, uint32_t addr) {
    asm volatile("ldmatrix.sync.aligned.m8n8.x4.shared.b16 {%0,%1,%2,%3}, [%4];"
                 : "=r"(d0), "=r"(d1), "=r"(d2), "=r"(d3) : "r"(addr));
}
__device__ __forceinline__ void mma_tf32(float c[4], uint32_t a0, uint32_t a1,
                                         uint32_t a2, uint32_t a3,
                                         uint32_t b0, uint32_t b1) {
    asm volatile("mma.sync.aligned.m16n8k8.row.col.f32.tf32.tf32.f32 "
                 "{%0,%1,%2,%3}, {%4,%5,%6,%7}, {%8,%9}, {%0,%1,%2,%3};"
                 : "+f"(c[0]), "+f"(c[1]), "+f"(c[2]), "+f"(c[3])
                 : "r"(a0), "r"(a1), "r"(a2), "r"(a3), "r"(b0), "r"(b1));
}
// swizzled 16B-chunk offset within a tile: row-major rows of 8 chunks, chunk
// column XOR'd with (row&7) -> ldmatrix and cp.async STS both conflict-free
__device__ __forceinline__ uint32_t tile_off(int row, int kc) {
    return (uint32_t)((row * 8 + (kc ^ (row & 7))) * 16);
}

// ---------------------------------------------------------------------------
// Kernel 1: g_WhT[h*64+b] = hidden[b,:]·W_w[h,:] + W_b[h] + U_b[h]
// ---------------------------------------------------------------------------
__global__ void __launch_bounds__(256, 4)
wh_kernel2(const float* __restrict__ hidden, const float* __restrict__ W_w,
           const float* __restrict__ W_b, const float* __restrict__ U_b) {
    __shared__ float4 sh[8][256];
    const int h0 = blockIdx.x * 8, b0 = blockIdx.y * 8;
    const int tid = threadIdx.x;
    for (int i = tid; i < 8 * 256; i += 256) {
        int bl = i >> 8, k4 = i & 255;
        sh[bl][k4] = reinterpret_cast<const float4*>(hidden)[(size_t)(b0 + bl) * 256 + k4];
    }
    __syncthreads();
    const int w = tid >> 5, lane = tid & 31;
    const int h = h0 + w;
    const float4* wrow = reinterpret_cast<const float4*>(W_w) + (size_t)h * 256;
    float acc[8] = {0.f, 0.f, 0.f, 0.f, 0.f, 0.f, 0.f, 0.f};
    for (int k4 = lane; k4 < 256; k4 += 32) {
        float4 wv = wrow[k4];
#pragma unroll
        for (int b = 0; b < 8; ++b) {
            float4 hv = sh[b][k4];
            acc[b] += wv.x * hv.x + wv.y * hv.y + wv.z * hv.z + wv.w * hv.w;
        }
    }
#pragma unroll
    for (int off = 16; off > 0; off >>= 1)
#pragma unroll
        for (int b = 0; b < 8; ++b) acc[b] += __shfl_xor_sync(0xffffffffu, acc[b], off);
    if (lane < 8)
        g_WhT[(size_t)h * 64 + b0 + lane] = acc[lane] + W_b[h] + U_b[h];
}

// ---------------------------------------------------------------------------
// Kernel 2: tf32 mma.sync GEMM (BM=128, BN=256, K=2048) + fused v·tanh epilogue.
// 256 threads = 8 warps (2m x 4n), warp tile 64x64, m16n8k8, ldmatrix feeds.
// grid (Hh/256 = 4, Mm/128 = 256): n-block fastest -> A tile L2 reuse.
// ---------------------------------------------------------------------------
__global__ void __launch_bounds__(256, 1)
gemm_energy_mma(const float* __restrict__ enc, const float* __restrict__ U_w,
                const float* __restrict__ v) {
    extern __shared__ char smem[];
    const uint32_t sbase = smem_u32(smem);

    const int tid = threadIdx.x;
    const int n0 = blockIdx.x * BN;
    const int m0 = blockIdx.y * BM;

    // ---- cp.async geometry (unchanged from validated R6 kernel)
    const int crow = tid >> 3, ckc = tid & 7;
    const char* srcA0 = (const char*)(enc + (size_t)(m0 + crow) * Kd + ckc * 4);
    const char* srcB0 = (const char*)(U_w + (size_t)(n0 + crow) * Kd + ckc * 4);
    const uint32_t dstA0 = tile_off(crow, ckc);
    const uint32_t dstB0 = (uint32_t)A_BYTES + tile_off(crow, ckc);
    constexpr size_t SRC_STEP = (size_t)32 * Kd * 4;
    constexpr uint32_t DST_STEP = 32 * 8 * 16;

    auto load_stage = [&](int t) {
        const uint32_t base = sbase + (uint32_t)(t % 3) * STG_BYTES;
        const size_t ko = (size_t)t * (BK * 4);
#pragma unroll
        for (int i = 0; i < 4; ++i)
            cp16(base + dstA0 + i * DST_STEP, srcA0 + ko + i * SRC_STEP);
#pragma unroll
        for (int i = 0; i < 8; ++i)
            cp16(base + dstB0 + i * DST_STEP, srcB0 + ko + i * SRC_STEP);
        cp_commit();
    };

    load_stage(0);
    load_stage(1);

    const int wid = tid >> 5, lane = tid & 31;
    const int wm = wid >> 2, wn = wid & 3;     // warp grid 2(m) x 4(n)
    const int gid = lane >> 2, tig = lane & 3;

    // ---- ldmatrix per-lane address precompute.
    // A x4 for tile mt: lanes 0-15 -> rows r0base+(lane&15) chunk kc0;
    //                   lanes 16-31 -> same rows, chunk kc1.
    //   d0..d3 = a0..a3 (8x8 b16 matrix == 8row x 4fp32col; lane l gets
    //   fp32 (l>>2, l&3) == tf32 fragment layout).
    // B x4 for nt pair p: m_id = lane>>3: {rows+0..7 kc0, rows kc1,
    //   rows+8 kc0, rows+8 kc1} -> d0..d3 = b[2p][0], b[2p][1], b[2p+1][0], b[2p+1][1].
    const uint32_t s7 = lane & 7;
    const uint32_t kcA = lane >> 4;            // 0/1
    const uint32_t kcB = (lane >> 3) & 1;      // 0/1
    uint32_t offA[4], offB[4];
#pragma unroll
    for (int mt = 0; mt < 4; ++mt)
        offA[mt] = (uint32_t)(wm * 64 + mt * 16 + (lane & 15)) * 128;
    const uint32_t rowBoff = (lane & 7) + ((lane >> 4) << 3);
#pragma unroll
    for (int p = 0; p < 4; ++p)
        offB[p] = (uint32_t)A_BYTES + (uint32_t)(wn * 64 + p * 16 + rowBoff) * 128;
    uint32_t coffA[4], coffB[4];
#pragma unroll
    for (int ks = 0; ks < 4; ++ks) {
        coffA[ks] = ((2 * ks + kcA) ^ s7) * 16;
        coffB[ks] = ((2 * ks + kcB) ^ s7) * 16;
    }

    float c[4][8][4];
#pragma unroll
    for (int mt = 0; mt < 4; ++mt)
#pragma unroll
        for (int nt = 0; nt < 8; ++nt)
#pragma unroll
            for (int k = 0; k < 4; ++k) c[mt][nt][k] = 0.f;

    for (int t = 0; t < NSTG; ++t) {
        if (t + 2 < NSTG) { load_stage(t + 2); cp_wait<2>(); }
        else if (t + 1 < NSTG) cp_wait<1>();
        else cp_wait<0>();
        __syncthreads();

        const uint32_t stb = sbase + (uint32_t)(t % 3) * STG_BYTES;

#pragma unroll
        for (int ks = 0; ks < 4; ++ks) {
            uint32_t a[4][4];
#pragma unroll
            for (int mt = 0; mt < 4; ++mt)
                ldm4(a[mt][0], a[mt][1], a[mt][2], a[mt][3],
                     stb + offA[mt] + coffA[ks]);
            uint32_t b[8][2];
#pragma unroll
            for (int p = 0; p < 4; ++p)
                ldm4(b[2 * p][0], b[2 * p][1], b[2 * p + 1][0], b[2 * p + 1][1],
                     stb + offB[p] + coffB[ks]);
#pragma unroll
            for (int mt = 0; mt < 4; ++mt)
#pragma unroll
                for (int nt = 0; nt < 8; ++nt)
                    mma_tf32(c[mt][nt], a[mt][0], a[mt][1], a[mt][2], a[mt][3],
                             b[nt][0], b[nt][1]);
        }
        __syncthreads();
    }

    // ---- fused epilogue: pe = sum over held cols of v[h]*tanh(C + WhT[h][b])
    float pe[4][2];
#pragma unroll
    for (int mt = 0; mt < 4; ++mt) { pe[mt][0] = 0.f; pe[mt][1] = 0.f; }

#pragma unroll
    for (int nt = 0; nt < 8; ++nt) {
        const int h0 = n0 + wn * 64 + nt * 8 + 2 * tig;
        const float vh0 = __ldg(&v[h0]);
        const float vh1 = __ldg(&v[h0 + 1]);
#pragma unroll
        for (int mt = 0; mt < 4; ++mt) {
#pragma unroll
            for (int half = 0; half < 2; ++half) {
                const int b = mt * 16 + half * 8 + gid;   // (m0+row)&63, wm drops out
                const float w0 = __ldg(&g_WhT[(size_t)h0 * 64 + b]);
                const float w1 = __ldg(&g_WhT[(size_t)(h0 + 1) * 64 + b]);
                pe[mt][half] += vh0 * tanhf(c[mt][nt][half * 2 + 0] + w0)
                              + vh1 * tanhf(c[mt][nt][half * 2 + 1] + w1);
            }
        }
    }

    float* sred = (float*)smem;   // reuse tile smem (mainloop finished, post-sync)
#pragma unroll
    for (int mt = 0; mt < 4; ++mt)
#pragma unroll
        for (int half = 0; half < 2; ++half) {
            float s = pe[mt][half];
            s += __shfl_xor_sync(0xffffffffu, s, 1);
            s += __shfl_xor_sync(0xffffffffu, s, 2);
            if (tig == 0)
                sred[wn * 128 + wm * 64 + mt * 16 + half * 8 + gid] = s;
        }
    __syncthreads();
    if (tid < 128) {
        float s = sred[tid] + sred[128 + tid] + sred[256 + tid] + sred[384 + tid];
        g_partial[(size_t)(m0 + tid) * 4 + blockIdx.x] = s;
    }
}

// ---------------------------------------------------------------------------
// Kernel 3: masked softmax over S per batch. grid 64, block 512.
// ---------------------------------------------------------------------------
__global__ void softmax_kernel(const int* __restrict__ mask, float* __restrict__ out) {
    const int b = blockIdx.x;
    const int s = threadIdx.x;
    const int m = s * Bb + b;
    float e = g_partial[(size_t)m * 4 + 0] + g_partial[(size_t)m * 4 + 1]
            + g_partial[(size_t)m * 4 + 2] + g_partial[(size_t)m * 4 + 3];
    if (mask[b * Ss + s] != 0) e = NEGV;

    __shared__ float red[512];
    red[s] = e;
    __syncthreads();
    for (int off = 256; off > 0; off >>= 1) {
        if (s < off) red[s] = fmaxf(red[s], red[s + off]);
        __syncthreads();
    }
    const float mx = red[0];
    __syncthreads();
    const float ex = __expf(e - mx);
    red[s] = ex;
    __syncthreads();
    for (int off = 256; off > 0; off >>= 1) {
        if (s < off) red[s] += red[s + off];
        __syncthreads();
    }
    out[b * Ss + s] = ex / red[0];
}

// ---------------------------------------------------------------------------
extern "C" void kernel_launch(void* const* d_in, const int* in_sizes, int n_in,
                              void* d_out, int out_size) {
    const float* hidden = (const float*)d_in[0];
    const float* enc    = (const float*)d_in[1];   // [S,B,2H] == [Mm,Kd]
    const int*   mask   = (const int*)d_in[2];
    const float* W_w    = (const float*)d_in[3];
    const float* W_b    = (const float*)d_in[4];
    const float* U_w    = (const float*)d_in[5];
    const float* U_b    = (const float*)d_in[6];
    const float* v_w    = (const float*)d_in[7];
    float* out = (float*)d_out;

    cudaFuncSetAttribute(gemm_energy_mma, cudaFuncAttributeMaxDynamicSharedMemorySize,
                         GEMM_SMEM);

    wh_kernel2<<<dim3(Hh / 8, Bb / 8), 256>>>(hidden, W_w, W_b, U_b);
    gemm_energy_mma<<<dim3(Hh / BN, Mm / BM), 256, GEMM_SMEM>>>(enc, U_w, v_w);
    softmax_kernel<<<Bb, 512>>>(mask, out);
}

// round 8
// speedup vs baseline: 6.9756x; 1.6018x over previous
#include <cuda_runtime.h>
#include <cuda_bf16.h>
#include <cstdint>
#include <math.h>

// Problem constants
constexpr int Bb = 64, Ss = 512, Hh = 1024, Kd = 2048, Mm = Bb * Ss;
#define NEGV -1e10f

// Scratch (no cudaMalloc allowed)
__device__ float g_WhT[Hh * Bb];      // WhT[h*64+b] = hidden@W^T + W_b + U_b (folded)
__device__ float g_partial[Mm * 4];   // per-(m, n-block) energy partials
__device__ __nv_bfloat16 g_encB[(size_t)Mm * Kd];   // 128 MB bf16 enc
__device__ __nv_bfloat16 g_UwB[(size_t)Hh * Kd];    // 4 MB bf16 U_w

// ---------------- GEMM tiling (bf16) ----------------
constexpr int BM = 128, BN = 256, BK = 64;     // BK=64 bf16 = 128B rows (same swizzle)
constexpr int NSTG = Kd / BK;                  // 32 K-stages
constexpr int A_BYTES = BM * BK * 2;           // 16 KB
constexpr int B_BYTES = BN * BK * 2;           // 32 KB
constexpr int STG_BYTES = A_BYTES + B_BYTES;   // 48 KB
constexpr int GEMM_SMEM = 3 * STG_BYTES;       // 144 KB (3-stage pipeline)

// ---------------- helpers ----------------
__device__ __forceinline__ uint32_t smem_u32(const void* p) {
    uint32_t a;
    asm("{ .reg .u64 t; cvta.to.shared.u64 t, %1; cvt.u32.u64 %0, t; }" : "=r"(a) : "l"(p));
    return a;
}
__device__ __forceinline__ void cp16(uint32_t dst, const void* src) {
    asm volatile("cp.async.cg.shared.global [%0], [%1], 16;" :: "r"(dst), "l"(src));
}
__device__ __forceinline__ void cp_commit() {
    asm volatile("cp.async.commit_group;" ::: "memory");
}
template <int N> __device__ __forceinline__ void cp_wait() {
    asm volatile("cp.async.wait_group %0;" :: "n"(N) : "memory");
}
__device__ __forceinline__ void ldm4(uint32_t& d0, uint32_t& d1, uint32_t& d2,
                                     uint32_t& d3, uint32_t addr) {
    asm volatile("ldmatrix.sync.aligned.m8n8.x4.shared.b16 {%0,%1,%2,%3}, [%4];"
                 : "=r"(d0), "=r"(d1), "=r"(d2), "=r"(d3) : "r"(addr));
}
__device__ __forceinline__ void mma_bf16(float c[4], uint32_t a0, uint32_t a1,
                                         uint32_t a2, uint32_t a3,
                                         uint32_t b0, uint32_t b1) {
    asm volatile("mma.sync.aligned.m16n8k16.row.col.f32.bf16.bf16.f32 "
                 "{%0,%1,%2,%3}, {%4,%5,%6,%7}, {%8,%9}, {%0,%1,%2,%3};"
                 : "+f"(c[0]), "+f"(c[1]), "+f"(c[2]), "+f"(c[3])
                 : "r"(a0), "r"(a1), "r"(a2), "r"(a3), "r"(b0), "r"(b1));
}
// swizzled 16B-chunk offset within a tile: rows of 8 chunks, chunk column
// XOR'd with (row&7) -> ldmatrix and cp.async STS both conflict-free
__device__ __forceinline__ uint32_t tile_off(int row, int kc) {
    return (uint32_t)((row * 8 + (kc ^ (row & 7))) * 16);
}

// ---------------------------------------------------------------------------
// Kernel 0: fp32 -> bf16 pre-conversion of enc and U_w (grid-stride, 8/thread)
// ---------------------------------------------------------------------------
__global__ void __launch_bounds__(256)
conv_bf16(const float* __restrict__ enc, const float* __restrict__ Uw) {
    const size_t ENC_G = ((size_t)Mm * Kd) / 8;
    const size_t TOT_G = ENC_G + ((size_t)Hh * Kd) / 8;
    for (size_t g = (size_t)blockIdx.x * blockDim.x + threadIdx.x; g < TOT_G;
         g += (size_t)gridDim.x * blockDim.x) {
        const float4* s;
        uint4* d;
        if (g < ENC_G) { s = (const float4*)enc + 2 * g; d = (uint4*)g_encB + g; }
        else { size_t g2 = g - ENC_G; s = (const float4*)Uw + 2 * g2; d = (uint4*)g_UwB + g2; }
        float4 a = s[0], b = s[1];
        __nv_bfloat162 p0 = __float22bfloat162_rn(make_float2(a.x, a.y));
        __nv_bfloat162 p1 = __float22bfloat162_rn(make_float2(a.z, a.w));
        __nv_bfloat162 p2 = __float22bfloat162_rn(make_float2(b.x, b.y));
        __nv_bfloat162 p3 = __float22bfloat162_rn(make_float2(b.z, b.w));
        uint4 o;
        o.x = *reinterpret_cast<unsigned*>(&p0);
        o.y = *reinterpret_cast<unsigned*>(&p1);
        o.z = *reinterpret_cast<unsigned*>(&p2);
        o.w = *reinterpret_cast<unsigned*>(&p3);
        *d = o;
    }
}

// ---------------------------------------------------------------------------
// Kernel 1: g_WhT[h*64+b] = hidden[b,:]·W_w[h,:] + W_b[h] + U_b[h]
// ---------------------------------------------------------------------------
__global__ void __launch_bounds__(256, 4)
wh_kernel2(const float* __restrict__ hidden, const float* __restrict__ W_w,
           const float* __restrict__ W_b, const float* __restrict__ U_b) {
    __shared__ float4 sh[8][256];
    const int h0 = blockIdx.x * 8, b0 = blockIdx.y * 8;
    const int tid = threadIdx.x;
    for (int i = tid; i < 8 * 256; i += 256) {
        int bl = i >> 8, k4 = i & 255;
        sh[bl][k4] = reinterpret_cast<const float4*>(hidden)[(size_t)(b0 + bl) * 256 + k4];
    }
    __syncthreads();
    const int w = tid >> 5, lane = tid & 31;
    const int h = h0 + w;
    const float4* wrow = reinterpret_cast<const float4*>(W_w) + (size_t)h * 256;
    float acc[8] = {0.f, 0.f, 0.f, 0.f, 0.f, 0.f, 0.f, 0.f};
    for (int k4 = lane; k4 < 256; k4 += 32) {
        float4 wv = wrow[k4];
#pragma unroll
        for (int b = 0; b < 8; ++b) {
            float4 hv = sh[b][k4];
            acc[b] += wv.x * hv.x + wv.y * hv.y + wv.z * hv.z + wv.w * hv.w;
        }
    }
#pragma unroll
    for (int off = 16; off > 0; off >>= 1)
#pragma unroll
        for (int b = 0; b < 8; ++b) acc[b] += __shfl_xor_sync(0xffffffffu, acc[b], off);
    if (lane < 8)
        g_WhT[(size_t)h * 64 + b0 + lane] = acc[lane] + W_b[h] + U_b[h];
}

// ---------------------------------------------------------------------------
// Kernel 2: bf16 mma.sync GEMM (BM=128, BN=256, K=2048) + fused v·tanh epilogue.
// 256 threads = 8 warps (2m x 4n), warp tile 64x64, m16n8k16, ldmatrix feeds.
// grid (Hh/256 = 4, Mm/128 = 256): n-block fastest -> A tile L2 reuse.
// ---------------------------------------------------------------------------
__global__ void __launch_bounds__(256, 1)
gemm_energy_mma(const float* __restrict__ v) {
    extern __shared__ char smem[];
    const uint32_t sbase = smem_u32(smem);

    const int tid = threadIdx.x;
    const int n0 = blockIdx.x * BN;
    const int m0 = blockIdx.y * BM;

    // ---- cp.async geometry: chunk idx = tid + i*256; row = idx>>3, kc = idx&7.
    // bf16 row = 64 elems = 128B (8 chunks of 16B) -> identical mapping to R7.
    const int crow = tid >> 3, ckc = tid & 7;
    const char* srcA0 = (const char*)(g_encB + (size_t)(m0 + crow) * Kd) + ckc * 16;
    const char* srcB0 = (const char*)(g_UwB + (size_t)(n0 + crow) * Kd) + ckc * 16;
    const uint32_t dstA0 = tile_off(crow, ckc);
    const uint32_t dstB0 = (uint32_t)A_BYTES + tile_off(crow, ckc);
    constexpr size_t SRC_STEP = (size_t)32 * Kd * 2;   // 32 rows of bf16
    constexpr uint32_t DST_STEP = 32 * 8 * 16;

    auto load_stage = [&](int t) {
        const uint32_t base = sbase + (uint32_t)(t % 3) * STG_BYTES;
        const size_t ko = (size_t)t * (BK * 2);        // 128 bytes per stage
#pragma unroll
        for (int i = 0; i < 4; ++i)
            cp16(base + dstA0 + i * DST_STEP, srcA0 + ko + i * SRC_STEP);
#pragma unroll
        for (int i = 0; i < 8; ++i)
            cp16(base + dstB0 + i * DST_STEP, srcB0 + ko + i * SRC_STEP);
        cp_commit();
    };

    load_stage(0);
    load_stage(1);

    const int wid = tid >> 5, lane = tid & 31;
    const int wm = wid >> 2, wn = wid & 3;     // warp grid 2(m) x 4(n)
    const int gid = lane >> 2, tig = lane & 3;

    // ---- ldmatrix per-lane addresses (canonical bf16 m16n8k16 fragments).
    // A x4 per mt: lanes 0-15 rows base+(lane&15) @kc0; lanes 16-31 same rows @kc1
    //   -> d0..d3 = a0..a3 of the k16 fragment (kc = 8-elem k-chunk).
    // B x4 per nt pair p: d0..d3 = b[2p][0], b[2p][1], b[2p+1][0], b[2p+1][1].
    const uint32_t s7 = lane & 7;
    const uint32_t kcA = lane >> 4;            // 0/1
    const uint32_t kcB = (lane >> 3) & 1;      // 0/1
    uint32_t offA[4], offB[4];
#pragma unroll
    for (int mt = 0; mt < 4; ++mt)
        offA[mt] = (uint32_t)(wm * 64 + mt * 16 + (lane & 15)) * 128;
    const uint32_t rowBoff = (lane & 7) + ((lane >> 4) << 3);
#pragma unroll
    for (int p = 0; p < 4; ++p)
        offB[p] = (uint32_t)A_BYTES + (uint32_t)(wn * 64 + p * 16 + rowBoff) * 128;
    uint32_t coffA[4], coffB[4];
#pragma unroll
    for (int ks = 0; ks < 4; ++ks) {           // ks = one k16 step = chunks 2ks, 2ks+1
        coffA[ks] = ((2 * ks + kcA) ^ s7) * 16;
        coffB[ks] = ((2 * ks + kcB) ^ s7) * 16;
    }

    float c[4][8][4];
#pragma unroll
    for (int mt = 0; mt < 4; ++mt)
#pragma unroll
        for (int nt = 0; nt < 8; ++nt)
#pragma unroll
            for (int k = 0; k < 4; ++k) c[mt][nt][k] = 0.f;

    for (int t = 0; t < NSTG; ++t) {
        if (t + 2 < NSTG) { load_stage(t + 2); cp_wait<2>(); }
        else if (t + 1 < NSTG) cp_wait<1>();
        else cp_wait<0>();
        __syncthreads();

        const uint32_t stb = sbase + (uint32_t)(t % 3) * STG_BYTES;

#pragma unroll
        for (int ks = 0; ks < 4; ++ks) {
            uint32_t a[4][4];
#pragma unroll
            for (int mt = 0; mt < 4; ++mt)
                ldm4(a[mt][0], a[mt][1], a[mt][2], a[mt][3],
                     stb + offA[mt] + coffA[ks]);
            uint32_t b[8][2];
#pragma unroll
            for (int p = 0; p < 4; ++p)
                ldm4(b[2 * p][0], b[2 * p][1], b[2 * p + 1][0], b[2 * p + 1][1],
                     stb + offB[p] + coffB[ks]);
#pragma unroll
            for (int mt = 0; mt < 4; ++mt)
#pragma unroll
                for (int nt = 0; nt < 8; ++nt)
                    mma_bf16(c[mt][nt], a[mt][0], a[mt][1], a[mt][2], a[mt][3],
                             b[nt][0], b[nt][1]);
        }
        __syncthreads();
    }

    // ---- fused epilogue: pe = sum over held cols of v[h]*tanh(C + WhT[h][b])
    float pe[4][2];
#pragma unroll
    for (int mt = 0; mt < 4; ++mt) { pe[mt][0] = 0.f; pe[mt][1] = 0.f; }

#pragma unroll
    for (int nt = 0; nt < 8; ++nt) {
        const int h0 = n0 + wn * 64 + nt * 8 + 2 * tig;
        const float vh0 = __ldg(&v[h0]);
        const float vh1 = __ldg(&v[h0 + 1]);
#pragma unroll
        for (int mt = 0; mt < 4; ++mt) {
#pragma unroll
            for (int half = 0; half < 2; ++half) {
                const int b = mt * 16 + half * 8 + gid;   // (m0+row)&63, wm drops out
                const float w0 = __ldg(&g_WhT[(size_t)h0 * 64 + b]);
                const float w1 = __ldg(&g_WhT[(size_t)(h0 + 1) * 64 + b]);
                pe[mt][half] += vh0 * tanhf(c[mt][nt][half * 2 + 0] + w0)
                              + vh1 * tanhf(c[mt][nt][half * 2 + 1] + w1);
            }
        }
    }

    float* sred = (float*)smem;   // reuse tile smem (mainloop finished, post-sync)
#pragma unroll
    for (int mt = 0; mt < 4; ++mt)
#pragma unroll
        for (int half = 0; half < 2; ++half) {
            float s = pe[mt][half];
            s += __shfl_xor_sync(0xffffffffu, s, 1);
            s += __shfl_xor_sync(0xffffffffu, s, 2);
            if (tig == 0)
                sred[wn * 128 + wm * 64 + mt * 16 + half * 8 + gid] = s;
        }
    __syncthreads();
    if (tid < 128) {
        float s = sred[tid] + sred[128 + tid] + sred[256 + tid] + sred[384 + tid];
        g_partial[(size_t)(m0 + tid) * 4 + blockIdx.x] = s;
    }
}

// ---------------------------------------------------------------------------
// Kernel 3: masked softmax over S per batch. grid 64, block 512.
// ---------------------------------------------------------------------------
__global__ void softmax_kernel(const int* __restrict__ mask, float* __restrict__ out) {
    const int b = blockIdx.x;
    const int s = threadIdx.x;
    const int m = s * Bb + b;
    float e = g_partial[(size_t)m * 4 + 0] + g_partial[(size_t)m * 4 + 1]
            + g_partial[(size_t)m * 4 + 2] + g_partial[(size_t)m * 4 + 3];
    if (mask[b * Ss + s] != 0) e = NEGV;

    __shared__ float red[512];
    red[s] = e;
    __syncthreads();
    for (int off = 256; off > 0; off >>= 1) {
        if (s < off) red[s] = fmaxf(red[s], red[s + off]);
        __syncthreads();
    }
    const float mx = red[0];
    __syncthreads();
    const float ex = __expf(e - mx);
    red[s] = ex;
    __syncthreads();
    for (int off = 256; off > 0; off >>= 1) {
        if (s < off) red[s] += red[s + off];
        __syncthreads();
    }
    out[b * Ss + s] = ex / red[0];
}

// ---------------------------------------------------------------------------
extern "C" void kernel_launch(void* const* d_in, const int* in_sizes, int n_in,
                              void* d_out, int out_size) {
    const float* hidden = (const float*)d_in[0];
    const float* enc    = (const float*)d_in[1];   // [S,B,2H] == [Mm,Kd]
    const int*   mask   = (const int*)d_in[2];
    const float* W_w    = (const float*)d_in[3];
    const float* W_b    = (const float*)d_in[4];
    const float* U_w    = (const float*)d_in[5];
    const float* U_b    = (const float*)d_in[6];
    const float* v_w    = (const float*)d_in[7];
    float* out = (float*)d_out;

    cudaFuncSetAttribute(gemm_energy_mma, cudaFuncAttributeMaxDynamicSharedMemorySize,
                         GEMM_SMEM);

    conv_bf16<<<16384, 256>>>(enc, U_w);
    wh_kernel2<<<dim3(Hh / 8, Bb / 8), 256>>>(hidden, W_w, W_b, U_b);
    gemm_energy_mma<<<dim3(Hh / BN, Mm / BM), 256, GEMM_SMEM>>>(v_w);
    softmax_kernel<<<Bb, 512>>>(mask, out);
}

// round 9
// speedup vs baseline: 7.4246x; 1.0644x over previous
#include <cuda_runtime.h>
#include <cuda_bf16.h>
#include <cstdint>
#include <math.h>

// Problem constants
constexpr int Bb = 64, Ss = 512, Hh = 1024, Kd = 2048, Mm = Bb * Ss;
#define NEGV -1e10f

// Scratch (no cudaMalloc allowed)
__device__ float g_WhT[Hh * Bb];      // WhT[h*64+b] = hidden@W^T + W_b + U_b (folded)
__device__ float g_partial[Mm * 4];   // per-(m, n-block) energy partials
__device__ __nv_bfloat16 g_encB[(size_t)Mm * Kd];   // 128 MB bf16 enc
__device__ __nv_bfloat16 g_UwB[(size_t)Hh * Kd];    // 4 MB bf16 U_w

// ---------------- GEMM tiling (bf16) ----------------
constexpr int BM = 128, BN = 256, BK = 64;     // BK=64 bf16 = 128B rows
constexpr int NSTG = Kd / BK;                  // 32 K-stages
constexpr int A_BYTES = BM * BK * 2;           // 16 KB
constexpr int B_BYTES = BN * BK * 2;           // 32 KB
constexpr int STG_BYTES = A_BYTES + B_BYTES;   // 48 KB
constexpr int NRING = 4;                       // 4-stage ring -> 1 barrier/stage
constexpr int GEMM_SMEM = NRING * STG_BYTES;   // 192 KB

// ---------------- helpers ----------------
__device__ __forceinline__ uint32_t smem_u32(const void* p) {
    uint32_t a;
    asm("{ .reg .u64 t; cvta.to.shared.u64 t, %1; cvt.u32.u64 %0, t; }" : "=r"(a) : "l"(p));
    return a;
}
__device__ __forceinline__ void cp16(uint32_t dst, const void* src) {
    asm volatile("cp.async.cg.shared.global [%0], [%1], 16;" :: "r"(dst), "l"(src));
}
__device__ __forceinline__ void cp_commit() {
    asm volatile("cp.async.commit_group;" ::: "memory");
}
template <int N> __device__ __forceinline__ void cp_wait() {
    asm volatile("cp.async.wait_group %0;" :: "n"(N) : "memory");
}
__device__ __forceinline__ void ldm4(uint32_t& d0, uint32_t& d1, uint32_t& d2,
                                     uint32_t& d3, uint32_t addr) {
    asm volatile("ldmatrix.sync.aligned.m8n8.x4.shared.b16 {%0,%1,%2,%3}, [%4];"
                 : "=r"(d0), "=r"(d1), "=r"(d2), "=r"(d3) : "r"(addr));
}
__device__ __forceinline__ void mma_bf16(float c[4], uint32_t a0, uint32_t a1,
                                         uint32_t a2, uint32_t a3,
                                         uint32_t b0, uint32_t b1) {
    asm volatile("mma.sync.aligned.m16n8k16.row.col.f32.bf16.bf16.f32 "
                 "{%0,%1,%2,%3}, {%4,%5,%6,%7}, {%8,%9}, {%0,%1,%2,%3};"
                 : "+f"(c[0]), "+f"(c[1]), "+f"(c[2]), "+f"(c[3])
                 : "r"(a0), "r"(a1), "r"(a2), "r"(a3), "r"(b0), "r"(b1));
}
// swizzled 16B-chunk offset within a tile: rows of 8 chunks, chunk column
// XOR'd with (row&7) -> ldmatrix and cp.async STS both conflict-free
__device__ __forceinline__ uint32_t tile_off(int row, int kc) {
    return (uint32_t)((row * 8 + (kc ^ (row & 7))) * 16);
}

// ---------------------------------------------------------------------------
// Kernel 0: fp32 -> bf16 pre-conversion of enc and U_w (grid-stride, 8/thread)
// ---------------------------------------------------------------------------
__global__ void __launch_bounds__(256)
conv_bf16(const float* __restrict__ enc, const float* __restrict__ Uw) {
    const size_t ENC_G = ((size_t)Mm * Kd) / 8;
    const size_t TOT_G = ENC_G + ((size_t)Hh * Kd) / 8;
    for (size_t g = (size_t)blockIdx.x * blockDim.x + threadIdx.x; g < TOT_G;
         g += (size_t)gridDim.x * blockDim.x) {
        const float4* s;
        uint4* d;
        if (g < ENC_G) { s = (const float4*)enc + 2 * g; d = (uint4*)g_encB + g; }
        else { size_t g2 = g - ENC_G; s = (const float4*)Uw + 2 * g2; d = (uint4*)g_UwB + g2; }
        float4 a = s[0], b = s[1];
        __nv_bfloat162 p0 = __float22bfloat162_rn(make_float2(a.x, a.y));
        __nv_bfloat162 p1 = __float22bfloat162_rn(make_float2(a.z, a.w));
        __nv_bfloat162 p2 = __float22bfloat162_rn(make_float2(b.x, b.y));
        __nv_bfloat162 p3 = __float22bfloat162_rn(make_float2(b.z, b.w));
        uint4 o;
        o.x = *reinterpret_cast<unsigned*>(&p0);
        o.y = *reinterpret_cast<unsigned*>(&p1);
        o.z = *reinterpret_cast<unsigned*>(&p2);
        o.w = *reinterpret_cast<unsigned*>(&p3);
        *d = o;
    }
}

// ---------------------------------------------------------------------------
// Kernel 1: g_WhT[h*64+b] = hidden[b,:]·W_w[h,:] + W_b[h] + U_b[h]
// ---------------------------------------------------------------------------
__global__ void __launch_bounds__(256, 4)
wh_kernel2(const float* __restrict__ hidden, const float* __restrict__ W_w,
           const float* __restrict__ W_b, const float* __restrict__ U_b) {
    __shared__ float4 sh[8][256];
    const int h0 = blockIdx.x * 8, b0 = blockIdx.y * 8;
    const int tid = threadIdx.x;
    for (int i = tid; i < 8 * 256; i += 256) {
        int bl = i >> 8, k4 = i & 255;
        sh[bl][k4] = reinterpret_cast<const float4*>(hidden)[(size_t)(b0 + bl) * 256 + k4];
    }
    __syncthreads();
    const int w = tid >> 5, lane = tid & 31;
    const int h = h0 + w;
    const float4* wrow = reinterpret_cast<const float4*>(W_w) + (size_t)h * 256;
    float acc[8] = {0.f, 0.f, 0.f, 0.f, 0.f, 0.f, 0.f, 0.f};
    for (int k4 = lane; k4 < 256; k4 += 32) {
        float4 wv = wrow[k4];
#pragma unroll
        for (int b = 0; b < 8; ++b) {
            float4 hv = sh[b][k4];
            acc[b] += wv.x * hv.x + wv.y * hv.y + wv.z * hv.z + wv.w * hv.w;
        }
    }
#pragma unroll
    for (int off = 16; off > 0; off >>= 1)
#pragma unroll
        for (int b = 0; b < 8; ++b) acc[b] += __shfl_xor_sync(0xffffffffu, acc[b], off);
    if (lane < 8)
        g_WhT[(size_t)h * 64 + b0 + lane] = acc[lane] + W_b[h] + U_b[h];
}

// ---------------------------------------------------------------------------
// Kernel 2: bf16 mma.sync GEMM (BM=128, BN=256, K=2048) + fused v·tanh epilogue.
// 512 threads = 16 warps (4m x 4n), warp tile 32x64, m16n8k16, ldmatrix feeds.
// 4-stage ring, prefetch depth 2, ONE __syncthreads per stage.
// grid (Hh/256 = 4, Mm/128 = 256): n-block fastest -> A tile L2 reuse.
// ---------------------------------------------------------------------------
__global__ void __launch_bounds__(512, 1)
gemm_energy_mma(const float* __restrict__ v) {
    extern __shared__ char smem[];
    const uint32_t sbase = smem_u32(smem);

    const int tid = threadIdx.x;
    const int n0 = blockIdx.x * BN;
    const int m0 = blockIdx.y * BM;

    // ---- cp.async geometry: 512 threads, 6 chunks/thread (2 A + 4 B).
    // chunk: row = crow + 64*i, kc = ckc (row&7 invariant under +64 -> same swizzle col)
    const int crow = tid >> 3, ckc = tid & 7;         // crow 0..63
    const char* srcA0 = (const char*)(g_encB + (size_t)(m0 + crow) * Kd) + ckc * 16;
    const char* srcB0 = (const char*)(g_UwB + (size_t)(n0 + crow) * Kd) + ckc * 16;
    const uint32_t dstA0 = tile_off(crow, ckc);
    const uint32_t dstB0 = (uint32_t)A_BYTES + tile_off(crow, ckc);
    constexpr size_t SRC_STEP = (size_t)64 * Kd * 2;  // 64 rows of bf16
    constexpr uint32_t DST_STEP = 64 * 8 * 16;        // 8192 B

    auto load_stage = [&](int t) {
        const uint32_t base = sbase + (uint32_t)(t & (NRING - 1)) * STG_BYTES;
        const size_t ko = (size_t)t * (BK * 2);       // 128 B per stage
#pragma unroll
        for (int i = 0; i < 2; ++i)
            cp16(base + dstA0 + i * DST_STEP, srcA0 + ko + i * SRC_STEP);
#pragma unroll
        for (int i = 0; i < 4; ++i)
            cp16(base + dstB0 + i * DST_STEP, srcB0 + ko + i * SRC_STEP);
        cp_commit();
    };

    load_stage(0);
    load_stage(1);

    const int wid = tid >> 5, lane = tid & 31;
    const int wm = wid >> 2, wn = wid & 3;     // warp grid 4(m) x 4(n)
    const int gid = lane >> 2, tig = lane & 3;

    // ---- ldmatrix per-lane addresses (canonical bf16 m16n8k16 fragments)
    const uint32_t s7 = lane & 7;
    const uint32_t kcA = lane >> 4;            // 0/1
    const uint32_t kcB = (lane >> 3) & 1;      // 0/1
    uint32_t offA[2], offB[4];
#pragma unroll
    for (int mt = 0; mt < 2; ++mt)
        offA[mt] = (uint32_t)(wm * 32 + mt * 16 + (lane & 15)) * 128;
    const uint32_t rowBoff = (lane & 7) + ((lane >> 4) << 3);
#pragma unroll
    for (int p = 0; p < 4; ++p)
        offB[p] = (uint32_t)A_BYTES + (uint32_t)(wn * 64 + p * 16 + rowBoff) * 128;
    uint32_t coffA[4], coffB[4];
#pragma unroll
    for (int ks = 0; ks < 4; ++ks) {           // ks = one k16 step = chunks 2ks, 2ks+1
        coffA[ks] = ((2 * ks + kcA) ^ s7) * 16;
        coffB[ks] = ((2 * ks + kcB) ^ s7) * 16;
    }

    float c[2][8][4];
#pragma unroll
    for (int mt = 0; mt < 2; ++mt)
#pragma unroll
        for (int nt = 0; nt < 8; ++nt)
#pragma unroll
            for (int k = 0; k < 4; ++k) c[mt][nt][k] = 0.f;

    for (int t = 0; t < NSTG; ++t) {
        // ring-4 + prefetch-2: load(t+2) writes slot (t-2)&3, whose last reader
        // (compute t-2) finished before the barrier below in iteration t-1.
        if (t + 2 < NSTG) { load_stage(t + 2); cp_wait<2>(); }
        else if (t + 1 < NSTG) cp_wait<1>();
        else cp_wait<0>();
        __syncthreads();

        const uint32_t stb = sbase + (uint32_t)(t & (NRING - 1)) * STG_BYTES;

#pragma unroll
        for (int ks = 0; ks < 4; ++ks) {
            uint32_t a[2][4];
#pragma unroll
            for (int mt = 0; mt < 2; ++mt)
                ldm4(a[mt][0], a[mt][1], a[mt][2], a[mt][3],
                     stb + offA[mt] + coffA[ks]);
            uint32_t b[8][2];
#pragma unroll
            for (int p = 0; p < 4; ++p)
                ldm4(b[2 * p][0], b[2 * p][1], b[2 * p + 1][0], b[2 * p + 1][1],
                     stb + offB[p] + coffB[ks]);
#pragma unroll
            for (int mt = 0; mt < 2; ++mt)
#pragma unroll
                for (int nt = 0; nt < 8; ++nt)
                    mma_bf16(c[mt][nt], a[mt][0], a[mt][1], a[mt][2], a[mt][3],
                             b[nt][0], b[nt][1]);
        }
    }

    // ---- fused epilogue: pe = sum over held cols of v[h]*tanh(C + WhT[h][b])
    float pe[2][2];
#pragma unroll
    for (int mt = 0; mt < 2; ++mt) { pe[mt][0] = 0.f; pe[mt][1] = 0.f; }

#pragma unroll
    for (int nt = 0; nt < 8; ++nt) {
        const int h0 = n0 + wn * 64 + nt * 8 + 2 * tig;
        const float vh0 = __ldg(&v[h0]);
        const float vh1 = __ldg(&v[h0 + 1]);
#pragma unroll
        for (int mt = 0; mt < 2; ++mt) {
#pragma unroll
            for (int half = 0; half < 2; ++half) {
                const int b = (wm * 32 + mt * 16 + half * 8 + gid) & 63;  // (m0+row)&63
                const float w0 = __ldg(&g_WhT[(size_t)h0 * 64 + b]);
                const float w1 = __ldg(&g_WhT[(size_t)(h0 + 1) * 64 + b]);
                pe[mt][half] += vh0 * tanhf(c[mt][nt][half * 2 + 0] + w0)
                              + vh1 * tanhf(c[mt][nt][half * 2 + 1] + w1);
            }
        }
    }

    // cross-warp reduction over the 4 n-warps (wn); smem reuse is safe: slot 0
    // (buf 0) was last read at stage NSTG-4, done before the final barrier.
    __syncthreads();
    float* sred = (float*)smem;
#pragma unroll
    for (int mt = 0; mt < 2; ++mt)
#pragma unroll
        for (int half = 0; half < 2; ++half) {
            float s = pe[mt][half];
            s += __shfl_xor_sync(0xffffffffu, s, 1);
            s += __shfl_xor_sync(0xffffffffu, s, 2);
            if (tig == 0)
                sred[wn * 128 + wm * 32 + mt * 16 + half * 8 + gid] = s;
        }
    __syncthreads();
    if (tid < 128) {
        float s = sred[tid] + sred[128 + tid] + sred[256 + tid] + sred[384 + tid];
        g_partial[(size_t)(m0 + tid) * 4 + blockIdx.x] = s;
    }
}

// ---------------------------------------------------------------------------
// Kernel 3: masked softmax over S per batch. grid 64, block 512.
// ---------------------------------------------------------------------------
__global__ void softmax_kernel(const int* __restrict__ mask, float* __restrict__ out) {
    const int b = blockIdx.x;
    const int s = threadIdx.x;
    const int m = s * Bb + b;
    float e = g_partial[(size_t)m * 4 + 0] + g_partial[(size_t)m * 4 + 1]
            + g_partial[(size_t)m * 4 + 2] + g_partial[(size_t)m * 4 + 3];
    if (mask[b * Ss + s] != 0) e = NEGV;

    __shared__ float red[512];
    red[s] = e;
    __syncthreads();
    for (int off = 256; off > 0; off >>= 1) {
        if (s < off) red[s] = fmaxf(red[s], red[s + off]);
        __syncthreads();
    }
    const float mx = red[0];
    __syncthreads();
    const float ex = __expf(e - mx);
    red[s] = ex;
    __syncthreads();
    for (int off = 256; off > 0; off >>= 1) {
        if (s < off) red[s] += red[s + off];
        __syncthreads();
    }
    out[b * Ss + s] = ex / red[0];
}

// ---------------------------------------------------------------------------
extern "C" void kernel_launch(void* const* d_in, const int* in_sizes, int n_in,
                              void* d_out, int out_size) {
    const float* hidden = (const float*)d_in[0];
    const float* enc    = (const float*)d_in[1];   // [S,B,2H] == [Mm,Kd]
    const int*   mask   = (const int*)d_in[2];
    const float* W_w    = (const float*)d_in[3];
    const float* W_b    = (const float*)d_in[4];
    const float* U_w    = (const float*)d_in[5];
    const float* U_b    = (const float*)d_in[6];
    const float* v_w    = (const float*)d_in[7];
    float* out = (float*)d_out;

    cudaFuncSetAttribute(gemm_energy_mma, cudaFuncAttributeMaxDynamicSharedMemorySize,
                         GEMM_SMEM);

    conv_bf16<<<16384, 256>>>(enc, U_w);
    wh_kernel2<<<dim3(Hh / 8, Bb / 8), 256>>>(hidden, W_w, W_b, U_b);
    gemm_energy_mma<<<dim3(Hh / BN, Mm / BM), 512, GEMM_SMEM>>>(v_w);
    softmax_kernel<<<Bb, 512>>>(mask, out);
}